// round 12
// baseline (speedup 1.0000x reference)
#include <cuda_runtime.h>
#include <cuda_bf16.h>
#include <cstdint>

// Problem constants (fixed shapes for TrivialDecoder_1236950581455)
#define E_GROUPS 65536
#define KNEG     16
#define GROUP    17
#define PAIRS    (E_GROUPS * GROUP)   // 1,114,112
#define D        64
#define KDIM     192
#define M_TILE   64                   // 4 warps x 16 rows
#define NTILE_TOT (PAIRS / M_TILE)    // 17408
#define THREADS  128                  // 4 warps
#define KSTEPS   6                    // 192 / 32 (fp8 k32 mma)
#define NTILES   8                    // 64 / 8
#define GRID_SC  296                  // 148 SMs x 2 CTAs (reg-limited)

#define APITCH   208                  // A: bytes per row (e4m3), conflict-free LDS
#define BPITCH   208                  // B staging: bytes per row (e4m3)

// SMEM byte layout (B staging used only in prologue)
#define SMEM_B1    0                          // 64 floats
#define SMEM_W2    256                        // 64 floats
#define SMEM_A     1024                       // 64 x 208 = 13312 B
#define SMEM_B     (1024 + 64 * APITCH)       // 64 x 208 = 13312 B
#define SMEM_TOTAL (SMEM_B + 64 * BPITCH)     // 27648

__device__ float g_scores[PAIRS];

__global__ void zero_out_kernel(float* out) { out[0] = 0.0f; }

// ---------------- portable PTX helpers ----------------
// cvt.e4m3x2: a -> high byte, b -> low byte. We want k-ascending in ascending bytes.
__device__ __forceinline__ uint32_t pack4_e4m3(float x0, float x1, float x2, float x3) {
    uint16_t lo, hi;
    asm("cvt.rn.satfinite.e4m3x2.f32 %0, %1, %2;" : "=h"(lo) : "f"(x1), "f"(x0));
    asm("cvt.rn.satfinite.e4m3x2.f32 %0, %1, %2;" : "=h"(hi) : "f"(x3), "f"(x2));
    return (uint32_t)lo | ((uint32_t)hi << 16);
}

__device__ __forceinline__ void mma_16832_e4m3(float* c, const uint32_t* a,
                                               uint32_t b0, uint32_t b1) {
    asm volatile(
        "mma.sync.aligned.m16n8k32.row.col.f32.e4m3.e4m3.f32 "
        "{%0,%1,%2,%3}, {%4,%5,%6,%7}, {%8,%9}, {%0,%1,%2,%3};"
        : "+f"(c[0]), "+f"(c[1]), "+f"(c[2]), "+f"(c[3])
        : "r"(a[0]), "r"(a[1]), "r"(a[2]), "r"(a[3]), "r"(b0), "r"(b1));
}

// ---------------------------------------------------------------------------
// Kernel 1: persistent, barrier-free warp pipelines; 4 warps x 16 m-rows.
// B (W1) fragments are REGISTER-RESIDENT: loaded once in the prologue
// (6 ks x 8 nt x 2 = 96 regs), reused for every tile -> zero B LDS in the
// steady-state loop. fp8 e4m3 mma, fp32 accumulate, W1 x8 -> epilogue x0.125.
// ---------------------------------------------------------------------------
__global__ void __launch_bounds__(THREADS, 2)
score_kernel(const float* __restrict__ embeds,
             const int*   __restrict__ pos,
             const int*   __restrict__ neg,
             const float* __restrict__ W1,
             const float* __restrict__ b1,
             const float* __restrict__ W2,
             const float* __restrict__ b2)
{
    extern __shared__ char smem[];
    const int tid = threadIdx.x;
    const int wid = tid >> 5;
    const int lid = tid & 31;
    const int g   = lid >> 2;          // fragment row/col group
    const int tg  = lid & 3;           // thread-in-group

    // One-time staging: b1, W2, W1 (e4m3 x8, plain 208B-pitch rows).
    if (tid < 64) {
        ((float*)(smem + SMEM_B1))[tid] = b1[tid];
        ((float*)(smem + SMEM_W2))[tid] = W2[tid];
    }
    for (int c = tid; c < 64 * 12; c += THREADS) {
        int n  = c / 12;
        int gq = c - n * 12;                    // 16-k chunk within row
        const float4* wp = (const float4*)(W1 + n * KDIM + gq * 16);
        float4 w0 = wp[0], w1 = wp[1], w2c = wp[2], w3 = wp[3];
        uint4 v = make_uint4(
            pack4_e4m3(w0.x * 8.0f, w0.y * 8.0f, w0.z * 8.0f, w0.w * 8.0f),
            pack4_e4m3(w1.x * 8.0f, w1.y * 8.0f, w1.z * 8.0f, w1.w * 8.0f),
            pack4_e4m3(w2c.x * 8.0f, w2c.y * 8.0f, w2c.z * 8.0f, w2c.w * 8.0f),
            pack4_e4m3(w3.x * 8.0f, w3.y * 8.0f, w3.z * 8.0f, w3.w * 8.0f));
        *(uint4*)(smem + SMEM_B + n * BPITCH + gq * 16) = v;
    }
    __syncthreads();   // only block barrier in the kernel

    // Load ALL B fragments into registers (persist across the tile loop).
    uint32_t breg[KSTEPS][NTILES][2];
    #pragma unroll
    for (int ks = 0; ks < KSTEPS; ks++) {
        #pragma unroll
        for (int nt = 0; nt < NTILES; nt++) {
            const char* br = smem + SMEM_B + (nt * 8 + g) * BPITCH + ks * 32 + tg * 4;
            breg[ks][nt][0] = *(const uint32_t*)(br);
            breg[ks][nt][1] = *(const uint32_t*)(br + 16);
        }
    }

    const float b2v = b2[0];
    const int q   = lid & 15;          // float4 slot within a 64-float row
    const int grp = lid >> 4;          // which of two rows per gather iter

    for (int t = blockIdx.x; t < NTILE_TOT; t += GRID_SC) {
        const int p0 = t * M_TILE;

        // ---- gather + convert: warp owns rows [16*wid, 16*wid+16) ----
        int iu_r = 0, iv_r = 0;
        if (lid < 16) {
            int p = p0 + wid * 16 + lid;
            unsigned e = (unsigned)p / 17u;
            unsigned j = (unsigned)p - e * 17u;
            const int* pr = (j == 0) ? (pos + 2 * e)
                                     : (neg + 2 * (e * KNEG + (j - 1)));
            iu_r = pr[0];
            iv_r = pr[1];
        }
        // Two batches of 4 iterations; each batch: issue 8 LDG.128, then convert.
        #pragma unroll
        for (int bt = 0; bt < 2; bt++) {
            float4 ub[4], vb[4];
            #pragma unroll
            for (int i = 0; i < 4; i++) {
                int src = 2 * (bt * 4 + i) + grp;           // local row 0..15
                int iu = __shfl_sync(0xffffffffu, iu_r, src);
                int iv = __shfl_sync(0xffffffffu, iv_r, src);
                ub[i] = ((const float4*)(embeds + (size_t)iu * 64))[q];
                vb[i] = ((const float4*)(embeds + (size_t)iv * 64))[q];
            }
            #pragma unroll
            for (int i = 0; i < 4; i++) {
                int src = 2 * (bt * 4 + i) + grp;
                float4 u4 = ub[i], v4 = vb[i];
                char* xr = smem + SMEM_A + (wid * 16 + src) * APITCH;
                *(uint32_t*)(xr + q * 4) =
                    pack4_e4m3(u4.x, u4.y, u4.z, u4.w);
                *(uint32_t*)(xr + 64 + q * 4) =
                    pack4_e4m3(v4.x, v4.y, v4.z, v4.w);
                *(uint32_t*)(xr + 128 + q * 4) =
                    pack4_e4m3(u4.x * v4.x, u4.y * v4.y, u4.z * v4.z, u4.w * v4.w);
            }
        }
        __syncwarp();   // order gather STS before cross-lane fragment LDS

        // ---- GEMM: warp tile 16(m) x 64(n), K=192; B from registers ----
        float c0[NTILES][4];
        #pragma unroll
        for (int nt = 0; nt < NTILES; nt++) {
            c0[nt][0] = c0[nt][1] = c0[nt][2] = c0[nt][3] = 0.0f;
        }
        #pragma unroll
        for (int ks = 0; ks < KSTEPS; ks++) {
            uint32_t a0[4];
            {
                const char* ar = smem + SMEM_A + (wid * 16 + g) * APITCH + ks * 32 + tg * 4;
                a0[0] = *(const uint32_t*)(ar);
                a0[1] = *(const uint32_t*)(ar + 8 * APITCH);
                a0[2] = *(const uint32_t*)(ar + 16);
                a0[3] = *(const uint32_t*)(ar + 8 * APITCH + 16);
            }
            #pragma unroll
            for (int nt = 0; nt < NTILES; nt++) {
                mma_16832_e4m3(c0[nt], a0, breg[ks][nt][0], breg[ks][nt][1]);
            }
        }

        // ---- epilogue in fragment layout (x0.125 undoes the W1 x8 scale) ----
        const float* b1s = (const float*)(smem + SMEM_B1);
        const float* w2s = (const float*)(smem + SMEM_W2);
        float z0 = 0.0f, z1 = 0.0f;
        #pragma unroll
        for (int nt = 0; nt < NTILES; nt++) {
            int n0 = nt * 8 + 2 * tg;
            float bb0 = b1s[n0], bb1 = b1s[n0 + 1];
            float ww0 = w2s[n0], ww1 = w2s[n0 + 1];
            float h;
            h = fmaf(c0[nt][0], 0.125f, bb0); h = h > 0.0f ? h : 0.0f; z0 += h * ww0;
            h = fmaf(c0[nt][1], 0.125f, bb1); h = h > 0.0f ? h : 0.0f; z0 += h * ww1;
            h = fmaf(c0[nt][2], 0.125f, bb0); h = h > 0.0f ? h : 0.0f; z1 += h * ww0;
            h = fmaf(c0[nt][3], 0.125f, bb1); h = h > 0.0f ? h : 0.0f; z1 += h * ww1;
        }
        z0 += __shfl_xor_sync(0xffffffffu, z0, 1);
        z0 += __shfl_xor_sync(0xffffffffu, z0, 2);
        z1 += __shfl_xor_sync(0xffffffffu, z1, 1);
        z1 += __shfl_xor_sync(0xffffffffu, z1, 2);

        if (tg == 0) {
            int r = p0 + wid * 16 + g;
            float s0 = 1.0f / (1.0f + expf(-(z0 + b2v)));
            float s1 = 1.0f / (1.0f + expf(-(z1 + b2v)));
            g_scores[r]     = expf(s0);
            g_scores[r + 8] = expf(s1);
        }
    }
}

// ---------------------------------------------------------------------------
// Kernel 2: per-group ratio + global reduction.
// ---------------------------------------------------------------------------
__global__ void __launch_bounds__(256)
loss_kernel(float* __restrict__ out)
{
    int e = blockIdx.x * blockDim.x + threadIdx.x;
    float term = 0.0f;
    if (e < E_GROUPS) {
        const float* s = g_scores + (long long)e * GROUP;
        float ps = s[0];
        float denom = ps;
        #pragma unroll
        for (int j = 1; j < GROUP; j++) denom += s[j];
        term = ps / (denom + 1e-8f) + 1e-8f;
    }
    #pragma unroll
    for (int o = 16; o; o >>= 1) term += __shfl_xor_sync(0xffffffffu, term, o);

    __shared__ float wsum[8];
    int l = threadIdx.x & 31;
    int w = threadIdx.x >> 5;
    if (l == 0) wsum[w] = term;
    __syncthreads();
    if (threadIdx.x < 8) {
        float t = wsum[threadIdx.x];
        #pragma unroll
        for (int o = 4; o; o >>= 1) t += __shfl_xor_sync(0x000000ffu, t, o);
        if (threadIdx.x == 0) atomicAdd(out, -t);
    }
}

extern "C" void kernel_launch(void* const* d_in, const int* in_sizes, int n_in,
                              void* d_out, int out_size)
{
    const float* embeds = (const float*)d_in[0];
    const int*   pos    = (const int*)  d_in[1];
    const int*   neg    = (const int*)  d_in[2];
    const float* W1     = (const float*)d_in[3];
    const float* b1     = (const float*)d_in[4];
    const float* W2     = (const float*)d_in[5];
    const float* b2     = (const float*)d_in[6];
    float*       out    = (float*)d_out;

    cudaFuncSetAttribute(score_kernel, cudaFuncAttributeMaxDynamicSharedMemorySize,
                         SMEM_TOTAL);

    // score first (independent of zeroing) so ncu's fixed skip lands on the
    // hot kernel; zero must still precede loss.
    score_kernel<<<GRID_SC, THREADS, SMEM_TOTAL>>>(embeds, pos, neg, W1, b1, W2, b2);
    zero_out_kernel<<<1, 1>>>(out);
    loss_kernel<<<E_GROUPS / 256, 256>>>(out);
}

// round 13
// speedup vs baseline: 1.5569x; 1.5569x over previous
#include <cuda_runtime.h>
#include <cuda_bf16.h>
#include <cstdint>

// Problem constants (fixed shapes for TrivialDecoder_1236950581455)
#define E_GROUPS 65536
#define KNEG     16
#define GROUP    17
#define PAIRS    (E_GROUPS * GROUP)   // 1,114,112
#define D        64
#define KDIM     192
#define M_TILE   128
#define NTILE_TOT (PAIRS / M_TILE)    // 8704
#define THREADS  256                  // 8 warps, each owns 16 m-rows
#define KSTEPS   6                    // 192 / 32 (fp8 k32 mma)
#define NTILES   8                    // 64 / 8
#define GRID_SC  444                  // 148 SMs x 3 CTAs

#define APITCH   208                  // A: bytes per row (e4m3), conflict-free LDS

// SMEM byte layout: total 39936 B -> 3 CTAs/SM
#define SMEM_B1    0                          // 64 floats
#define SMEM_W2    256                        // 64 floats
#define SMEM_A     1024                       // 128 x 208 = 26624 B
#define SMEM_B     (1024 + 128 * APITCH)      // packed B: 1536 x 8 = 12288 B
#define SMEM_TOTAL (SMEM_B + 12288)           // 39936

__device__ float g_scores[PAIRS];

__global__ void zero_out_kernel(float* out) { out[0] = 0.0f; }

// ---------------- portable PTX helpers ----------------
// cvt.e4m3x2: a -> high byte, b -> low byte. We want k-ascending in ascending bytes.
__device__ __forceinline__ uint32_t pack4_e4m3(float x0, float x1, float x2, float x3) {
    uint16_t lo, hi;
    asm("cvt.rn.satfinite.e4m3x2.f32 %0, %1, %2;" : "=h"(lo) : "f"(x1), "f"(x0));
    asm("cvt.rn.satfinite.e4m3x2.f32 %0, %1, %2;" : "=h"(hi) : "f"(x3), "f"(x2));
    return (uint32_t)lo | ((uint32_t)hi << 16);
}

__device__ __forceinline__ void mma_16832_e4m3(float* c, const uint32_t* a,
                                               uint32_t b0, uint32_t b1) {
    asm volatile(
        "mma.sync.aligned.m16n8k32.row.col.f32.e4m3.e4m3.f32 "
        "{%0,%1,%2,%3}, {%4,%5,%6,%7}, {%8,%9}, {%0,%1,%2,%3};"
        : "+f"(c[0]), "+f"(c[1]), "+f"(c[2]), "+f"(c[3])
        : "r"(a[0]), "r"(a[1]), "r"(a[2]), "r"(a[3]), "r"(b0), "r"(b1));
}

// ---------------------------------------------------------------------------
// Kernel 1: persistent, barrier-free warp pipelines; 8 warps x 16 m-rows.
// B (W1) stored PACKED in shared: one uint2 per (nt,ks,lane) so the two
// fragment words load as a single 8-byte LDS (B-LDS halved vs R11).
// fp8 e4m3 mma, fp32 accumulate, W1 x8 -> epilogue x0.125.
// ---------------------------------------------------------------------------
__global__ void __launch_bounds__(THREADS, 3)
score_kernel(const float* __restrict__ embeds,
             const int*   __restrict__ pos,
             const int*   __restrict__ neg,
             const float* __restrict__ W1,
             const float* __restrict__ b1,
             const float* __restrict__ W2,
             const float* __restrict__ b2)
{
    extern __shared__ char smem[];
    const int tid = threadIdx.x;
    const int wid = tid >> 5;
    const int lid = tid & 31;
    const int g   = lid >> 2;          // fragment row/col group
    const int tg  = lid & 3;           // thread-in-group

    // One-time staging: b1, W2 to shared.
    if (tid < 64) {
        ((float*)(smem + SMEM_B1))[tid] = b1[tid];
        ((float*)(smem + SMEM_W2))[tid] = W2[tid];
    }
    // Stage W1 as PACKED e4m3 fragment entries (scaled x8).
    // Entry index e = ((nt*6 + ks)*8 + gg)*4 + tt  holds uint2:
    //   { e4m3x4 of W1[n][ks*32 + tt*4 ..], e4m3x4 of W1[n][ks*32+16+tt*4 ..] }
    // with n = nt*8 + gg.
    for (int c = tid; c < 64 * 24; c += THREADS) {
        int n   = c / 24;
        int rem = c - n * 24;
        int ks  = rem >> 2;
        int tt  = rem & 3;
        int nt  = n >> 3;
        int gg  = n & 7;
        const float4* wp0 = (const float4*)(W1 + n * KDIM + ks * 32 + tt * 4);
        const float4* wp1 = (const float4*)(W1 + n * KDIM + ks * 32 + 16 + tt * 4);
        float4 w0 = *wp0, w1 = *wp1;
        uint2 v = make_uint2(
            pack4_e4m3(w0.x * 8.0f, w0.y * 8.0f, w0.z * 8.0f, w0.w * 8.0f),
            pack4_e4m3(w1.x * 8.0f, w1.y * 8.0f, w1.z * 8.0f, w1.w * 8.0f));
        int e = ((nt * 6 + ks) * 8 + gg) * 4 + tt;
        *(uint2*)(smem + SMEM_B + e * 8) = v;
    }
    __syncthreads();   // only block barrier in the kernel

    const float b2v = b2[0];
    const int q   = lid & 15;          // float4 slot within a 64-float row
    const int grp = lid >> 4;          // which of two rows per gather iter

    for (int t = blockIdx.x; t < NTILE_TOT; t += GRID_SC) {
        const int p0 = t * M_TILE;

        // ---- gather + convert: warp owns rows [16*wid, 16*wid+16) ----
        int iu_r = 0, iv_r = 0;
        if (lid < 16) {
            int p = p0 + wid * 16 + lid;
            unsigned e = (unsigned)p / 17u;
            unsigned j = (unsigned)p - e * 17u;
            const int* pr = (j == 0) ? (pos + 2 * e)
                                     : (neg + 2 * (e * KNEG + (j - 1)));
            iu_r = pr[0];
            iv_r = pr[1];
        }
        // Two batches of 4 iterations; each batch: issue 8 LDG.128, then convert.
        #pragma unroll
        for (int bt = 0; bt < 2; bt++) {
            float4 ub[4], vb[4];
            #pragma unroll
            for (int i = 0; i < 4; i++) {
                int src = 2 * (bt * 4 + i) + grp;           // local row 0..15
                int iu = __shfl_sync(0xffffffffu, iu_r, src);
                int iv = __shfl_sync(0xffffffffu, iv_r, src);
                ub[i] = ((const float4*)(embeds + (size_t)iu * 64))[q];
                vb[i] = ((const float4*)(embeds + (size_t)iv * 64))[q];
            }
            #pragma unroll
            for (int i = 0; i < 4; i++) {
                int src = 2 * (bt * 4 + i) + grp;
                float4 u4 = ub[i], v4 = vb[i];
                char* xr = smem + SMEM_A + (wid * 16 + src) * APITCH;
                *(uint32_t*)(xr + q * 4) =
                    pack4_e4m3(u4.x, u4.y, u4.z, u4.w);
                *(uint32_t*)(xr + 64 + q * 4) =
                    pack4_e4m3(v4.x, v4.y, v4.z, v4.w);
                *(uint32_t*)(xr + 128 + q * 4) =
                    pack4_e4m3(u4.x * v4.x, u4.y * v4.y, u4.z * v4.z, u4.w * v4.w);
            }
        }
        __syncwarp();   // order gather STS before cross-lane fragment LDS

        // ---- GEMM: warp tile 16(m) x 64(n), K=192; B via packed 8B LDS ----
        float c0[NTILES][4];
        #pragma unroll
        for (int nt = 0; nt < NTILES; nt++) {
            c0[nt][0] = c0[nt][1] = c0[nt][2] = c0[nt][3] = 0.0f;
        }
        #pragma unroll
        for (int ks = 0; ks < KSTEPS; ks++) {
            uint32_t a0[4];
            {
                const char* ar = smem + SMEM_A + (wid * 16 + g) * APITCH + ks * 32 + tg * 4;
                a0[0] = *(const uint32_t*)(ar);
                a0[1] = *(const uint32_t*)(ar + 8 * APITCH);
                a0[2] = *(const uint32_t*)(ar + 16);
                a0[3] = *(const uint32_t*)(ar + 8 * APITCH + 16);
            }
            #pragma unroll
            for (int nt = 0; nt < NTILES; nt++) {
                uint2 b = *(const uint2*)(smem + SMEM_B
                                          + ((nt * 6 + ks) * 32 + lid) * 8);
                mma_16832_e4m3(c0[nt], a0, b.x, b.y);
            }
        }

        // ---- epilogue in fragment layout (x0.125 undoes the W1 x8 scale) ----
        const float* b1s = (const float*)(smem + SMEM_B1);
        const float* w2s = (const float*)(smem + SMEM_W2);
        float z0 = 0.0f, z1 = 0.0f;
        #pragma unroll
        for (int nt = 0; nt < NTILES; nt++) {
            int n0 = nt * 8 + 2 * tg;
            float bb0 = b1s[n0], bb1 = b1s[n0 + 1];
            float ww0 = w2s[n0], ww1 = w2s[n0 + 1];
            float h;
            h = fmaf(c0[nt][0], 0.125f, bb0); h = h > 0.0f ? h : 0.0f; z0 += h * ww0;
            h = fmaf(c0[nt][1], 0.125f, bb1); h = h > 0.0f ? h : 0.0f; z0 += h * ww1;
            h = fmaf(c0[nt][2], 0.125f, bb0); h = h > 0.0f ? h : 0.0f; z1 += h * ww0;
            h = fmaf(c0[nt][3], 0.125f, bb1); h = h > 0.0f ? h : 0.0f; z1 += h * ww1;
        }
        z0 += __shfl_xor_sync(0xffffffffu, z0, 1);
        z0 += __shfl_xor_sync(0xffffffffu, z0, 2);
        z1 += __shfl_xor_sync(0xffffffffu, z1, 1);
        z1 += __shfl_xor_sync(0xffffffffu, z1, 2);

        if (tg == 0) {
            int r = p0 + wid * 16 + g;
            float s0 = 1.0f / (1.0f + expf(-(z0 + b2v)));
            float s1 = 1.0f / (1.0f + expf(-(z1 + b2v)));
            g_scores[r]     = expf(s0);
            g_scores[r + 8] = expf(s1);
        }
    }
}

// ---------------------------------------------------------------------------
// Kernel 2: per-group ratio + global reduction.
// ---------------------------------------------------------------------------
__global__ void __launch_bounds__(256)
loss_kernel(float* __restrict__ out)
{
    int e = blockIdx.x * blockDim.x + threadIdx.x;
    float term = 0.0f;
    if (e < E_GROUPS) {
        const float* s = g_scores + (long long)e * GROUP;
        float ps = s[0];
        float denom = ps;
        #pragma unroll
        for (int j = 1; j < GROUP; j++) denom += s[j];
        term = ps / (denom + 1e-8f) + 1e-8f;
    }
    #pragma unroll
    for (int o = 16; o; o >>= 1) term += __shfl_xor_sync(0xffffffffu, term, o);

    __shared__ float wsum[8];
    int l = threadIdx.x & 31;
    int w = threadIdx.x >> 5;
    if (l == 0) wsum[w] = term;
    __syncthreads();
    if (threadIdx.x < 8) {
        float t = wsum[threadIdx.x];
        #pragma unroll
        for (int o = 4; o; o >>= 1) t += __shfl_xor_sync(0x000000ffu, t, o);
        if (threadIdx.x == 0) atomicAdd(out, -t);
    }
}

extern "C" void kernel_launch(void* const* d_in, const int* in_sizes, int n_in,
                              void* d_out, int out_size)
{
    const float* embeds = (const float*)d_in[0];
    const int*   pos    = (const int*)  d_in[1];
    const int*   neg    = (const int*)  d_in[2];
    const float* W1     = (const float*)d_in[3];
    const float* b1     = (const float*)d_in[4];
    const float* W2     = (const float*)d_in[5];
    const float* b2     = (const float*)d_in[6];
    float*       out    = (float*)d_out;

    cudaFuncSetAttribute(score_kernel, cudaFuncAttributeMaxDynamicSharedMemorySize,
                         SMEM_TOTAL);

    // score first (independent of zeroing) so ncu's fixed skip lands on the
    // hot kernel; zero must still precede loss.
    score_kernel<<<GRID_SC, THREADS, SMEM_TOTAL>>>(embeds, pos, neg, W1, b1, W2, b2);
    zero_out_kernel<<<1, 1>>>(out);
    loss_kernel<<<E_GROUPS / 256, 256>>>(out);
}